// round 16
// baseline (speedup 1.0000x reference)
#include <cuda_runtime.h>
#include <math.h>
#include <stdint.h>

// XSReLU_cw_perc_param: out = relu(x - thr[b,c]),
//   thr = s[k_lo] + (s[k_hi] - s[k_lo]) * sigmoid(plogit[c]),
//   s = sorted row (4096 elems), k_lo/k_hi from sigmoid(plogit[0]) +/- 0.02.
// Dual radix select, 4 x 8-bit passes. Branch-free hot loops via predicated
// PTX atomics (no BSSY/BSYNC). Pass-1 compacts survivors into a shared buffer
// so passes 2/3 touch only ~survivor elements. Packed 16|16 dual histograms.

#define ROW_LEN 4096
#define THREADS 256
#define PER_THR 16

__device__ __forceinline__ unsigned f2s(float f) {
    unsigned u = __float_as_uint(f);
    return u ^ ((unsigned)(((int)u) >> 31) | 0x80000000u);
}
__device__ __forceinline__ float s2f(unsigned u) {
    unsigned m = (~(unsigned)(((int)u) >> 31)) | 0x80000000u;
    return __uint_as_float(u ^ m);
}

// if (add != 0) smem[saddr] += add;   -- predicated, no divergent branch
__device__ __forceinline__ void red_shared_if(unsigned add, unsigned saddr) {
    asm volatile("{\n\t.reg .pred p;\n\t"
                 "setp.ne.u32 p, %0, 0;\n\t"
                 "@p red.shared.add.u32 [%1], %0;\n\t}"
                 :: "r"(add), "r"(saddr) : "memory");
}

// if (pred) { i = (*cnt)++; *(u32*)(base + i*stride) = val; }  -- predicated
__device__ __forceinline__ void push_if(unsigned pred, unsigned cnt_saddr,
                                        unsigned base_saddr, int stride_bytes,
                                        unsigned val) {
    asm volatile("{\n\t.reg .pred p; .reg .u32 r;\n\t"
                 "setp.ne.u32 p, %0, 0;\n\t"
                 "@p atom.shared.add.u32 r, [%1], 1;\n\t"
                 "@p mad.lo.s32 r, r, %3, %2;\n\t"
                 "@p st.shared.u32 [r], %4;\n\t}"
                 :: "r"(pred), "r"(cnt_saddr), "r"(base_saddr),
                    "r"((unsigned)stride_bytes), "r"(val) : "memory");
}

// Packed dual scan + select over 256 bins, warp 0 only.
// hist fields: lo = bits[0:16), hi = bits[16:32).
// After return: sel[0]=binLo, sel[1]=residLo, sel[2]=binHi, sel[3]=residHi.
__device__ __forceinline__ void pscan(const unsigned* __restrict__ h_,
                                      unsigned* sel, int tid,
                                      unsigned rLo, unsigned rHi) {
    if (tid < 32) {
        const uint4* hv = reinterpret_cast<const uint4*>(h_);
        uint4 a = hv[2 * tid], c = hv[2 * tid + 1];
        unsigned hb[8] = {a.x, a.y, a.z, a.w, c.x, c.y, c.z, c.w};
        unsigned local = 0;
        #pragma unroll
        for (int i = 0; i < 8; ++i) local += hb[i];
        unsigned inc = local;                       // packed scan, fields <= 4096
        #pragma unroll
        for (int s = 1; s < 32; s <<= 1) {
            unsigned n = __shfl_up_sync(0xffffffffu, inc, s);
            if (tid >= s) inc += n;
        }
        unsigned excl = inc - local;
        unsigned exLo = excl & 0xFFFFu, exHi = excl >> 16;
        #pragma unroll
        for (int b = 0; b < 8; ++b) {
            unsigned hLo = hb[b] & 0xFFFFu, hHi = hb[b] >> 16;
            if (rLo - exLo < hLo) { sel[0] = 8u * tid + b; sel[1] = rLo - exLo; }
            if (rHi - exHi < hHi) { sel[2] = 8u * tid + b; sel[3] = rHi - exHi; }
            exLo += hLo; exHi += hHi;
        }
    }
    __syncthreads();
}

__global__ void __launch_bounds__(THREADS, 6)
XSReLU_cw_perc_param_47528108097997_kernel(const float* __restrict__ x,
                                           const float* __restrict__ plogit,
                                           float* __restrict__ out, int C) {
    __shared__ __align__(16) unsigned h0[256];
    __shared__ __align__(16) unsigned h1[256];
    __shared__ __align__(16) unsigned h2[256];
    __shared__ __align__(16) unsigned h3[256];
    __shared__ __align__(16) unsigned buf[ROW_LEN];   // survivor compaction
    __shared__ unsigned cnt[2];                       // Lo head, Hi head
    __shared__ unsigned sel[4];

    const int row = blockIdx.x;
    const int tid = threadIdx.x;

    const float4* __restrict__ xr =
        reinterpret_cast<const float4*>(x) + (size_t)row * (ROW_LEN / 4);
    float4* __restrict__ orow =
        reinterpret_cast<float4*>(out) + (size_t)row * (ROW_LEN / 4);

    // shared-space addresses for predicated asm
    const unsigned h1b  = (unsigned)__cvta_generic_to_shared(h1);
    const unsigned h2b  = (unsigned)__cvta_generic_to_shared(h2);
    const unsigned h3b  = (unsigned)__cvta_generic_to_shared(h3);
    const unsigned bufb = (unsigned)__cvta_generic_to_shared(buf);
    const unsigned buft = bufb + 4u * (ROW_LEN - 1);
    const unsigned cnt0 = (unsigned)__cvta_generic_to_shared(&cnt[0]);
    const unsigned cnt1 = (unsigned)__cvta_generic_to_shared(&cnt[1]);

    // ---- load row (coalesced float4) -> order-preserving uint keys
    unsigned u[PER_THR];
    #pragma unroll
    for (int j = 0; j < 4; ++j) {
        float4 t = xr[tid + j * THREADS];
        u[4 * j + 0] = f2s(t.x);
        u[4 * j + 1] = f2s(t.y);
        u[4 * j + 2] = f2s(t.z);
        u[4 * j + 3] = f2s(t.w);
    }

    // ---- clear histograms + counters
    h0[tid] = 0; h1[tid] = 0; h2[tid] = 0; h3[tid] = 0;
    if (tid < 2) cnt[tid] = 0;

    // ---- ranks (f32 arithmetic + trunc cast to match jnp)
    const float p0 = 1.0f / (1.0f + expf(-plogit[0]));
    const unsigned rLo0 =
        (unsigned)min(max((int)(4096.0f * (p0 - 0.02f)), 0), ROW_LEN - 1);
    const unsigned rHi0 =
        (unsigned)min(max((int)(4096.0f * (p0 + 0.02f)), 0), ROW_LEN - 1);
    __syncthreads();

    // ========== pass 0: byte3, unconditional packed red ==========
    #pragma unroll
    for (int j = 0; j < PER_THR; ++j)
        atomicAdd(&h0[u[j] >> 24], 0x10001u);     // return unused -> RED, no branch
    __syncthreads();
    pscan(h0, sel, tid, rLo0, rHi0);
    const unsigned bLo = sel[0], bHi = sel[2];
    unsigned rLo = sel[1], rHi = sel[3];
    const unsigned hiPush = (bLo != bHi);         // same-bin: Hi reuses Lo buffer

    // ========== pass 1: byte2, gated count + survivor compaction ==========
    #pragma unroll
    for (int j = 0; j < PER_THR; ++j) {
        unsigned w   = u[j];
        unsigned b0  = w >> 24;
        unsigned eLo = (b0 == bLo);
        unsigned eHi = (b0 == bHi);
        red_shared_if(eLo + (eHi << 16), h1b + 4u * ((w >> 16) & 0xFFu));
        push_if(eLo,          cnt0, bufb,  4, w);
        push_if(eHi & hiPush, cnt1, buft, -4, w);
    }
    __syncthreads();
    const unsigned nLo = cnt[0];
    const unsigned nHi = hiPush ? cnt[1] : nLo;
    pscan(h1, sel, tid, rLo, rHi);
    unsigned pLo = (bLo << 8) | sel[0];
    unsigned pHi = (bHi << 8) | sel[2];
    rLo = sel[1]; rHi = sel[3];

    // ========== pass 2: byte1, over survivors only ==========
    for (unsigned i = tid; i < nLo; i += THREADS) {
        unsigned w = buf[i];
        red_shared_if((unsigned)((w >> 16) == pLo), h2b + 4u * ((w >> 8) & 0xFFu));
    }
    for (unsigned i = tid; i < nHi; i += THREADS) {
        unsigned w = hiPush ? buf[ROW_LEN - 1 - i] : buf[i];
        red_shared_if(((unsigned)((w >> 16) == pHi)) << 16, h2b + 4u * ((w >> 8) & 0xFFu));
    }
    __syncthreads();
    pscan(h2, sel, tid, rLo, rHi);
    pLo = (pLo << 8) | sel[0];
    pHi = (pHi << 8) | sel[2];
    rLo = sel[1]; rHi = sel[3];

    // ========== pass 3: byte0, over survivors only ==========
    for (unsigned i = tid; i < nLo; i += THREADS) {
        unsigned w = buf[i];
        red_shared_if((unsigned)((w >> 8) == pLo), h3b + 4u * (w & 0xFFu));
    }
    for (unsigned i = tid; i < nHi; i += THREADS) {
        unsigned w = hiPush ? buf[ROW_LEN - 1 - i] : buf[i];
        red_shared_if(((unsigned)((w >> 8) == pHi)) << 16, h3b + 4u * (w & 0xFFu));
    }
    __syncthreads();
    pscan(h3, sel, tid, rLo, rHi);

    // ---- threshold + fused epilogue (floats recomputed bit-exactly)
    const float xl  = s2f((pLo << 8) | sel[0]);
    const float xh  = s2f((pHi << 8) | sel[2]);
    const int   c   = ((C & (C - 1)) == 0) ? (row & (C - 1)) : (row % C);
    const float pc  = 1.0f / (1.0f + expf(-plogit[c]));
    const float thr = xl + (xh - xl) * pc;

    #pragma unroll
    for (int j = 0; j < 4; ++j) {
        float4 t;
        t.x = fmaxf(s2f(u[4 * j + 0]) - thr, 0.0f);
        t.y = fmaxf(s2f(u[4 * j + 1]) - thr, 0.0f);
        t.z = fmaxf(s2f(u[4 * j + 2]) - thr, 0.0f);
        t.w = fmaxf(s2f(u[4 * j + 3]) - thr, 0.0f);
        orow[tid + j * THREADS] = t;
    }
}

extern "C" void kernel_launch(void* const* d_in, const int* in_sizes, int n_in,
                              void* d_out, int out_size) {
    const float* x      = (const float*)d_in[0];   // [B, C, H, W] f32
    const float* plogit = (const float*)d_in[1];   // [C] f32
    float*       out    = (float*)d_out;

    const int total = in_sizes[0];                 // B*C*H*W
    const int C     = in_sizes[1];                 // 256
    const int rows  = total / ROW_LEN;             // B*C

    XSReLU_cw_perc_param_47528108097997_kernel<<<rows, THREADS>>>(x, plogit, out, C);
}

// round 17
// speedup vs baseline: 1.1193x; 1.1193x over previous
#include <cuda_runtime.h>
#include <math.h>
#include <stdint.h>

// XSReLU_cw_perc_param: out = relu(x - thr[b,c]),
//   thr = s[k_lo] + (s[k_hi] - s[k_lo]) * sigmoid(plogit[c]),
//   s = sorted row (4096 elems), ranks from sigmoid(plogit[0]) +/- 0.02.
// Dual radix select, 12/10/10 bits. Pass A: 4096-bin histogram, plain RED
// (low conflict at 12 bits). Bank-conflict-free strided layout, all-warp
// scan with single-thread bin walk. Pass B compacts the ~100 A-survivors
// into the dead pass-A histogram; pass C runs over survivors only.

#define ROW_LEN 4096
#define THREADS 256
#define PER_THR 16

__device__ __forceinline__ unsigned f2s(float f) {
    unsigned u = __float_as_uint(f);
    return u ^ ((unsigned)(((int)u) >> 31) | 0x80000000u);
}
__device__ __forceinline__ float s2f(unsigned u) {
    unsigned m = (~(unsigned)(((int)u) >> 31)) | 0x80000000u;
    return __uint_as_float(u ^ m);
}

// if (add != 0) smem[saddr] += add;   -- predicated, no divergent branch
__device__ __forceinline__ void red_shared_if(unsigned add, unsigned saddr) {
    asm volatile("{\n\t.reg .pred p;\n\t"
                 "setp.ne.u32 p, %0, 0;\n\t"
                 "@p red.shared.add.u32 [%1], %0;\n\t}"
                 :: "r"(add), "r"(saddr) : "memory");
}

// if (pred) { i = (*cnt)++; *(u32*)(base + 4*i) = val; }  -- predicated
__device__ __forceinline__ void push_if(unsigned pred, unsigned cnt_saddr,
                                        unsigned base_saddr, unsigned val) {
    asm volatile("{\n\t.reg .pred p; .reg .u32 r;\n\t"
                 "setp.ne.u32 p, %0, 0;\n\t"
                 "@p atom.shared.add.u32 r, [%1], 1;\n\t"
                 "@p mad.lo.s32 r, r, 4, %2;\n\t"
                 "@p st.shared.u32 [r], %3;\n\t}"
                 :: "r"(pred), "r"(cnt_saddr), "r"(base_saddr), "r"(val)
                 : "memory");
}

// Histogram slot mapping: digit d, NBT bins per thread; owner t = d/NBT,
// sub-bin i = d%NBT, slot = i*256 + t  (stride-256 scalar LDS -> conflict-free).
// Packed 16|16 dual scan + select, all warps; only the rank-owning thread
// walks its NBT bins. Results in sel[0..3] after the trailing barrier.
template<int NBT>
__device__ __forceinline__ void pselect(const unsigned* __restrict__ h,
                                        unsigned* warp_sums, unsigned* sel,
                                        int tid, int lane, int wid,
                                        unsigned rLo, unsigned rHi) {
    unsigned local = 0;
    #pragma unroll
    for (int i = 0; i < NBT; ++i) local += h[i * 256 + tid];
    unsigned inc = local;                          // packed scan, fields <= 4096
    #pragma unroll
    for (int s = 1; s < 32; s <<= 1) {
        unsigned n = __shfl_up_sync(0xffffffffu, inc, s);
        if (lane >= s) inc += n;
    }
    if (lane == 31) warp_sums[wid] = inc;
    __syncthreads();
    unsigned off = 0;
    #pragma unroll
    for (int w = 0; w < 8; ++w)
        if (w < wid) off += warp_sums[w];
    const unsigned ex   = off + inc - local;
    unsigned exLo = ex & 0xFFFFu, exHi = ex >> 16;
    const unsigned locLo = local & 0xFFFFu, locHi = local >> 16;

    if (rLo - exLo < locLo) {                      // exactly one thread
        #pragma unroll
        for (int i = 0; i < NBT; ++i) {
            unsigned hLo = h[i * 256 + tid] & 0xFFFFu;
            if (rLo - exLo < hLo) { sel[0] = (unsigned)tid * NBT + i; sel[1] = rLo - exLo; break; }
            exLo += hLo;
        }
    }
    if (rHi - exHi < locHi) {                      // exactly one thread
        #pragma unroll
        for (int i = 0; i < NBT; ++i) {
            unsigned hHi = h[i * 256 + tid] >> 16;
            if (rHi - exHi < hHi) { sel[2] = (unsigned)tid * NBT + i; sel[3] = rHi - exHi; break; }
            exHi += hHi;
        }
    }
    __syncthreads();
}

__global__ void __launch_bounds__(THREADS, 6)
XSReLU_cw_perc_param_47528108097997_kernel(const float* __restrict__ x,
                                           const float* __restrict__ plogit,
                                           float* __restrict__ out, int C) {
    __shared__ __align__(16) unsigned hA[4096];    // 12-bit pass; reused as survivor buf
    __shared__ __align__(16) unsigned hB[1024];
    __shared__ __align__(16) unsigned hC[1024];
    __shared__ unsigned warp_sums[8];
    __shared__ unsigned sel[4];
    __shared__ unsigned cnt;

    const int row  = blockIdx.x;
    const int tid  = threadIdx.x;
    const int lane = tid & 31;
    const int wid  = tid >> 5;

    const float4* __restrict__ xr =
        reinterpret_cast<const float4*>(x) + (size_t)row * (ROW_LEN / 4);
    float4* __restrict__ orow =
        reinterpret_cast<float4*>(out) + (size_t)row * (ROW_LEN / 4);

    const unsigned hBb  = (unsigned)__cvta_generic_to_shared(hB);
    const unsigned hCb  = (unsigned)__cvta_generic_to_shared(hC);
    const unsigned bufb = (unsigned)__cvta_generic_to_shared(hA);
    const unsigned cntb = (unsigned)__cvta_generic_to_shared(&cnt);

    // ---- load row (coalesced float4) -> order-preserving uint keys
    unsigned u[PER_THR];
    #pragma unroll
    for (int j = 0; j < 4; ++j) {
        float4 t = xr[tid + j * THREADS];
        u[4 * j + 0] = f2s(t.x);
        u[4 * j + 1] = f2s(t.y);
        u[4 * j + 2] = f2s(t.z);
        u[4 * j + 3] = f2s(t.w);
    }

    // ---- clear histograms + counter
    uint4 z = make_uint4(0, 0, 0, 0);
    #pragma unroll
    for (int k = 0; k < 4; ++k) reinterpret_cast<uint4*>(hA)[tid + THREADS * k] = z;
    reinterpret_cast<uint4*>(hB)[tid] = z;
    reinterpret_cast<uint4*>(hC)[tid] = z;
    if (tid == 0) cnt = 0;

    // ---- ranks (f32 arithmetic + trunc cast to match jnp)
    const float p0 = 1.0f / (1.0f + expf(-plogit[0]));
    const unsigned rLo0 =
        (unsigned)min(max((int)(4096.0f * (p0 - 0.02f)), 0), ROW_LEN - 1);
    const unsigned rHi0 =
        (unsigned)min(max((int)(4096.0f * (p0 + 0.02f)), 0), ROW_LEN - 1);
    __syncthreads();

    // ========== pass A: bits[31:20], 4096 bins, plain packed RED ==========
    #pragma unroll
    for (int j = 0; j < PER_THR; ++j) {
        unsigned d = u[j] >> 20;                               // 12-bit digit
        atomicAdd(&hA[((d & 15u) << 8) | (d >> 4)], 0x10001u); // strided slot
    }
    __syncthreads();
    pselect<16>(hA, warp_sums, sel, tid, lane, wid, rLo0, rHi0);
    const unsigned bALo = sel[0], bAHi = sel[2];
    unsigned rLo = sel[1], rHi = sel[3];

    // ========== pass B: bits[19:10], gated; compact survivors into hA ======
    // (hA is dead as a histogram after pselect's trailing barrier)
    #pragma unroll
    for (int j = 0; j < PER_THR; ++j) {
        unsigned w   = u[j];
        unsigned dA  = w >> 20;
        unsigned eLo = (dA == bALo);
        unsigned eHi = (dA == bAHi);
        unsigned d   = (w >> 10) & 0x3FFu;
        red_shared_if(eLo + (eHi << 16), hBb + 4u * (((d & 3u) << 8) | (d >> 2)));
        push_if(eLo | eHi, cntb, bufb, w);
    }
    __syncthreads();
    const unsigned nU = cnt;
    pselect<4>(hB, warp_sums, sel, tid, lane, wid, rLo, rHi);
    const unsigned pLo = (bALo << 10) | sel[0];   // 22-bit prefixes
    const unsigned pHi = (bAHi << 10) | sel[2];
    rLo = sel[1]; rHi = sel[3];

    // ========== pass C: bits[9:0], survivors only (~100 elements) ==========
    for (unsigned i = tid; i < nU; i += THREADS) {
        unsigned w   = hA[i];
        unsigned t22 = w >> 10;
        unsigned d   = w & 0x3FFu;
        red_shared_if((unsigned)(t22 == pLo) + ((unsigned)(t22 == pHi) << 16),
                      hCb + 4u * (((d & 3u) << 8) | (d >> 2)));
    }
    __syncthreads();
    pselect<4>(hC, warp_sums, sel, tid, lane, wid, rLo, rHi);

    // ---- threshold + fused epilogue (floats recomputed bit-exactly)
    const float xl  = s2f((pLo << 10) | sel[0]);
    const float xh  = s2f((pHi << 10) | sel[2]);
    const int   c   = ((C & (C - 1)) == 0) ? (row & (C - 1)) : (row % C);
    const float pc  = 1.0f / (1.0f + expf(-plogit[c]));
    const float thr = xl + (xh - xl) * pc;

    #pragma unroll
    for (int j = 0; j < 4; ++j) {
        float4 t;
        t.x = fmaxf(s2f(u[4 * j + 0]) - thr, 0.0f);
        t.y = fmaxf(s2f(u[4 * j + 1]) - thr, 0.0f);
        t.z = fmaxf(s2f(u[4 * j + 2]) - thr, 0.0f);
        t.w = fmaxf(s2f(u[4 * j + 3]) - thr, 0.0f);
        orow[tid + j * THREADS] = t;
    }
}

extern "C" void kernel_launch(void* const* d_in, const int* in_sizes, int n_in,
                              void* d_out, int out_size) {
    const float* x      = (const float*)d_in[0];   // [B, C, H, W] f32
    const float* plogit = (const float*)d_in[1];   // [C] f32
    float*       out    = (float*)d_out;

    const int total = in_sizes[0];                 // B*C*H*W
    const int C     = in_sizes[1];                 // 256
    const int rows  = total / ROW_LEN;             // B*C

    XSReLU_cw_perc_param_47528108097997_kernel<<<rows, THREADS>>>(x, plogit, out, C);
}